// round 11
// baseline (speedup 1.0000x reference)
#include <cuda_runtime.h>
#include <math.h>

#define Dn   512
#define FDn  2048
#define On   256
#define Kn   49
#define Bn   4
#define Cn   256
#define Hn   64
#define Wn   48
#define HWn  3072
#define Nn   32
#define KOn  (Kn*On)     // 12544
#define KOP  16384       // padded 64*256
#define BSPLIT 4
#define GST  260         // k_GAB smem row stride

typedef unsigned long long u64;

__device__ float g_eps [Nn*FDn];
__device__ float g_v   [Nn*Dn];
__device__ float g_bvec[Nn*KOP];          // k padded to 64; slots >=49*256 stay 0
__device__ float g_A   [Hn*On];
__device__ float g_Bm  [Wn*On];
__device__ float g_eGA [Nn*Kn*Hn];
__device__ float g_eGB [Nn*Kn*Wn];
__device__ float g_eapp[Bn*Kn*HWn];

__device__ __forceinline__ void ffma2(u64 &acc, u64 a, u64 b) {
    asm volatile("fma.rn.f32x2 %0, %1, %2, %0;" : "+l"(acc) : "l"(a), "l"(b));
}
__device__ __forceinline__ float hsum2(u64 a) {
    float2 f = *reinterpret_cast<float2*>(&a);
    return f.x + f.y;
}

__device__ __forceinline__ float embed_val(float z, int dd) {
    float e = (dd < 256) ? (2.0f*dd + 1.0f)*(1.0f/512.0f) : (2.0f*(dd-256))*(1.0f/512.0f);
    float invden = exp2f(-e * 9.96578428466209f);   // 1000^-e
    double a = (double)z * (double)invden;
    double k = rint(a * 0.15915494309189535);
    float  r = (float)(a - k * 6.2831853071795864769);
    return (dd < 256) ? sinf(r) : cosf(r);
}

// blocks: 0..31 eps | 32..47 A/B tiled GEMM | 48,49 zero g_v | 50..65 zero g_bvec
__global__ void k_pre(const float* __restrict__ rois,
                      const float* __restrict__ W_im) {
    __shared__ __align__(16) float smp[64*130 + 32*130];  // pe + W tile (49.9 KB)
    int bid = blockIdx.x;
    if (bid < Nn) {
        int n = bid;
        float c0 = rois[n*5+1], c1 = rois[n*5+2], c2 = rois[n*5+3], c3 = rois[n*5+4];
        for (int i = threadIdx.x; i < FDn; i += blockDim.x) {
            int c  = i >> 9;
            int dd = i & 511;
            float z = (c >= 2) ? ((c == 3) ? c3 : c2) : ((c == 1) ? c1 : c0);
            g_eps[n*FDn + i] = embed_val(z, dd);
        }
    } else if (bid < Nn + 16) {
        // ---- A/B: out[j,o] = sum_f pe[j,f] * W_im[o, side*512 + f] ----
        float* pe_s = smp;              // [64 j][130]
        float* w_s  = smp + 64*130;     // [32 o][130]
        int t    = bid - Nn;
        int side = t >> 3;              // 0=A (j:64), 1=B (j:48)
        int o0   = (t & 7) * 32;
        int nj   = side ? Wn : Hn;
        int ol = threadIdx.x & 31, jg = threadIdx.x >> 5;
        u64 acc[8] = {0,0,0,0,0,0,0,0};
        for (int fs = 0; fs < 4; ++fs) {
            int f0 = fs * 128;
            __syncthreads();
            for (int i = threadIdx.x; i < nj*128; i += 256) {
                int j = i >> 7, fl = i & 127;
                pe_s[j*130 + fl] = embed_val((float)j, f0 + fl);
            }
            {
                int srow = threadIdx.x >> 5, scol = threadIdx.x & 31;
                #pragma unroll
                for (int p = 0; p < 4; ++p) {
                    int row = p*8 + srow;
                    float4 wv = *(const float4*)(W_im + (size_t)(o0 + row)*(2*Dn)
                                                 + side*Dn + f0 + scol*4);
                    float* dst = w_s + row*130 + scol*4;
                    *(float2*)(dst)     = make_float2(wv.x, wv.y);
                    *(float2*)(dst + 2) = make_float2(wv.z, wv.w);
                }
            }
            __syncthreads();
            const float* wrow = w_s + ol*130;
            if (side == 0) {
                #pragma unroll 4
                for (int fq = 0; fq < 32; ++fq) {
                    u64 w0 = *(const u64*)(wrow + fq*4);
                    u64 w1 = *(const u64*)(wrow + fq*4 + 2);
                    #pragma unroll
                    for (int jj = 0; jj < 8; ++jj) {
                        const float* pr = pe_s + (jg*8 + jj)*130 + fq*4;
                        ffma2(acc[jj], w0, *(const u64*)pr);
                        ffma2(acc[jj], w1, *(const u64*)(pr + 2));
                    }
                }
            } else {
                #pragma unroll 4
                for (int fq = 0; fq < 32; ++fq) {
                    u64 w0 = *(const u64*)(wrow + fq*4);
                    u64 w1 = *(const u64*)(wrow + fq*4 + 2);
                    #pragma unroll
                    for (int jj = 0; jj < 6; ++jj) {
                        const float* pr = pe_s + (jg*6 + jj)*130 + fq*4;
                        ffma2(acc[jj], w0, *(const u64*)pr);
                        ffma2(acc[jj], w1, *(const u64*)(pr + 2));
                    }
                }
            }
        }
        int o = o0 + ol;
        if (side == 0) {
            #pragma unroll
            for (int jj = 0; jj < 8; ++jj)
                g_A[(jg*8 + jj)*On + o] = hsum2(acc[jj]);
        } else {
            #pragma unroll
            for (int jj = 0; jj < 6; ++jj)
                g_Bm[(jg*6 + jj)*On + o] = hsum2(acc[jj]);
        }
    } else if (bid < Nn + 18) {
        int half = bid - (Nn + 16);
        int base = half * (Nn*Dn/2);
        for (int i = threadIdx.x; i < Nn*Dn/2; i += 256)
            g_v[base + i] = 0.0f;
    } else {
        int seg = bid - (Nn + 18);     // 0..15
        int base = seg * (Nn*KOP/16);
        for (int i = threadIdx.x; i < Nn*KOP/16; i += 256)
            g_bvec[base + i] = 0.0f;
    }
}

// ================= fused v (blocks 0..255) + app (blocks 256..447) =============
__global__ void k_vapp(const float* __restrict__ V_box,
                       const float* __restrict__ x,
                       const float* __restrict__ conv_w,
                       const float* __restrict__ conv_b) {
    extern __shared__ __align__(16) float sm[];
    int bx = blockIdx.x;
    if (bx < 256) {
        // ---------------- v role ----------------
        float* eps_s = sm;             // [32 n][128 f]
        float* vt_s  = sm + 32*128;    // [32 d][130]
        int dp = bx >> 4, ks = bx & 15;
        int f0 = ks * 128;
        for (int i = threadIdx.x; i < 32*128; i += 256) {
            int n = i >> 7, f = i & 127;
            eps_s[i] = g_eps[n*FDn + f0 + f];
        }
        int srow = threadIdx.x >> 5, scol = threadIdx.x & 31;
        #pragma unroll
        for (int p = 0; p < 4; ++p) {
            int row = p*8 + srow;
            float4 vv = *(const float4*)(V_box + (size_t)(dp*32 + row)*FDn + f0 + scol*4);
            float* dst = vt_s + row*130 + scol*4;
            *(float2*)(dst)     = make_float2(vv.x, vv.y);
            *(float2*)(dst + 2) = make_float2(vv.z, vv.w);
        }
        __syncthreads();
        int dl = threadIdx.x & 31, ng = threadIdx.x >> 5;
        int d  = dp*32 + dl, n0 = ng*4;
        u64 acc[4] = {0,0,0,0};
        const float* vrow = vt_s + dl*130;
        #pragma unroll 8
        for (int fq = 0; fq < 32; ++fq) {
            u64 w0 = *(const u64*)(vrow + fq*4);
            u64 w1 = *(const u64*)(vrow + fq*4 + 2);
            #pragma unroll
            for (int j = 0; j < 4; ++j) {
                ulonglong2 ev = *(const ulonglong2*)(eps_s + (n0+j)*128 + fq*4);
                ffma2(acc[j], w0, ev.x);
                ffma2(acc[j], w1, ev.y);
            }
        }
        #pragma unroll
        for (int j = 0; j < 4; ++j)
            atomicAdd(&g_v[(size_t)(n0+j)*Dn + d], hsum2(acc[j]));
    } else {
        // ------- app role: c-vectorized; thread = (kq 0..3 x px 0..63), 13 k's --
        float* cw_s = sm;              // [52 k][256 c] (rows >=49 zero)
        float* x_s  = sm + 52*256;     // [64 px][34]  (32 c chunk + pad 2)
        int r   = bx - 256;
        int b   = r / 48;
        int px0 = (r - b*48) * 64;
        for (int i = threadIdx.x; i < 52*256; i += 256) {
            int k = i >> 8, c = i & 255;
            cw_s[i] = (k < Kn) ? conv_w[k*Cn + c] : 0.0f;
        }
        int px = threadIdx.x & 63;
        int kq = threadIdx.x >> 6;     // 0..3
        u64 acc[13];
        #pragma unroll
        for (int kk = 0; kk < 13; ++kk) acc[kk] = 0;

        for (int c0 = 0; c0 < Cn; c0 += 32) {
            __syncthreads();
            for (int i = threadIdx.x; i < 32*64; i += 256) {
                int c = i >> 6, p = i & 63;
                x_s[p*34 + c] = x[((size_t)b*Cn + c0 + c)*HWn + px0 + p];
            }
            __syncthreads();
            #pragma unroll
            for (int c4 = 0; c4 < 8; ++c4) {
                u64 x01 = *(const u64*)(x_s + px*34 + c4*4);
                u64 x23 = *(const u64*)(x_s + px*34 + c4*4 + 2);
                #pragma unroll
                for (int kk = 0; kk < 13; ++kk) {
                    float4 w4 = *(const float4*)(cw_s + (kq*13 + kk)*256 + c0 + c4*4);
                    u64 w01 = ((const u64*)&w4)[0];
                    u64 w23 = ((const u64*)&w4)[1];
                    ffma2(acc[kk], w01, x01);
                    ffma2(acc[kk], w23, x23);
                }
            }
        }
        #pragma unroll
        for (int kk = 0; kk < 13; ++kk) {
            int k = kq*13 + kk;
            if (k < Kn)
                g_eapp[((size_t)b*Kn + k)*HWn + px0 + px] =
                    expf(hsum2(acc[kk]) + conv_b[k]);
        }
    }
}

// ---------------- bvec: grid (196 ko-tiles, 4 d-slices), atomic reduce ----------
__global__ void k_bvec(const float* __restrict__ W_box) {
    extern __shared__ __align__(16) float smb[];
    float* v_s  = smb;            // [32 n][128 f]
    float* wt_s = smb + 32*128;   // [64 ko][130]
    int ks = blockIdx.y;
    int f0 = ks * 128;
    int ko0 = blockIdx.x * 64;
    for (int i = threadIdx.x; i < 32*128; i += 256) {
        int n = i >> 7, fl = i & 127;
        v_s[i] = g_v[n*Dn + f0 + fl];
    }
    int srow = threadIdx.x >> 5, scol = threadIdx.x & 31;
    #pragma unroll
    for (int p = 0; p < 8; ++p) {
        int row = p*8 + srow;
        float4 wv = *(const float4*)(W_box + (size_t)(ko0 + row)*Dn + f0 + scol*4);
        float* dst = wt_s + row*130 + scol*4;
        *(float2*)(dst)     = make_float2(wv.x, wv.y);
        *(float2*)(dst + 2) = make_float2(wv.z, wv.w);
    }
    __syncthreads();
    int kol = threadIdx.x & 63;
    int ng  = threadIdx.x >> 6;
    int n0  = ng * 8;
    int ko  = ko0 + kol;
    int k   = ko >> 8, o = ko & 255;
    const float* wrow = wt_s + kol*130;
    u64 acc[8] = {0,0,0,0,0,0,0,0};
    #pragma unroll 4
    for (int fq = 0; fq < 32; ++fq) {
        u64 w0 = *(const u64*)(wrow + fq*4);
        u64 w1 = *(const u64*)(wrow + fq*4 + 2);
        #pragma unroll
        for (int j = 0; j < 8; ++j) {
            ulonglong2 vv = *(const ulonglong2*)(v_s + (n0+j)*128 + fq*4);
            ffma2(acc[j], w0, vv.x);
            ffma2(acc[j], w1, vv.y);
        }
    }
    #pragma unroll
    for (int j = 0; j < 8; ++j)
        atomicAdd(&g_bvec[(size_t)(n0+j)*KOP + k*256 + o], hsum2(acc[j]));
}

// -------- eGA/eGB: register-tiled GEMM, grid (n, side, lz*2+kz) ----------------
__global__ void __launch_bounds__(256, 2) k_GAB() {
    extern __shared__ __align__(16) float smg[];
    float* M_s  = smg;             // 32*GST
    float* bv_s = smg + 32*GST;    // 32*GST
    int n  = blockIdx.x;
    bool isA = (blockIdx.y == 0);
    int lz = blockIdx.z >> 1, kz = blockIdx.z & 1;
    int L    = isA ? Hn : Wn;
    int rows = isA ? 32 : 24;
    int loff = lz * rows;
    int k0   = kz * 32;
    const float* src = isA ? g_A : g_Bm;
    for (int i = threadIdx.x; i < rows*64; i += 256) {
        int r = i >> 6, o4 = i & 63;
        *(float4*)(M_s + r*GST + o4*4) =
            *(const float4*)(src + (size_t)(loff + r)*On + o4*4);
    }
    for (int i = threadIdx.x; i < 32*64; i += 256) {
        int r = i >> 6, o4 = i & 63;
        *(float4*)(bv_s + r*GST + o4*4) =
            *(const float4*)(g_bvec + (size_t)n*KOP + (size_t)(k0 + r)*On + o4*4);
    }
    __syncthreads();
    int lq = threadIdx.x & 15, kq = threadIdx.x >> 4;
    const float* m0 = M_s + lq*GST;
    const float* m1 = M_s + (lq + 16)*GST;
    const float* b0 = bv_s + (kq*2)*GST;
    const float* b1 = b0 + GST;
    float a00=0.f, a01=0.f, a10=0.f, a11=0.f;
    #pragma unroll 8
    for (int o4 = 0; o4 < 64; ++o4) {
        float4 ma = *(const float4*)(m0 + o4*4);
        float4 mb = *(const float4*)(m1 + o4*4);
        float4 ba = *(const float4*)(b0 + o4*4);
        float4 bb = *(const float4*)(b1 + o4*4);
        a00 += ma.x*ba.x + ma.y*ba.y + ma.z*ba.z + ma.w*ba.w;
        a01 += ma.x*bb.x + ma.y*bb.y + ma.z*bb.z + ma.w*bb.w;
        a10 += mb.x*ba.x + mb.y*ba.y + mb.z*ba.z + mb.w*ba.w;
        a11 += mb.x*bb.x + mb.y*bb.y + mb.z*bb.z + mb.w*bb.w;
    }
    int l0 = loff + lq;
    int l1 = loff + lq + 16;
    int k  = k0 + kq*2;
    bool l1ok = (lq + 16) < rows;
    float* dst = isA ? (g_eGA + (size_t)n*Kn*Hn) : (g_eGB + (size_t)n*Kn*Wn);
    if (k < Kn) {
        dst[k*L + l0] = expf(a00);
        if (l1ok) dst[k*L + l1] = expf(a10);
    }
    if (k + 1 < Kn) {
        dst[(k+1)*L + l0] = expf(a01);
        if (l1ok) dst[(k+1)*L + l1] = expf(a11);
    }
}

// ---------------- final: 4 px/thread, float4 I/O, softmax over k ----------------
__global__ void k_final(const float* __restrict__ rois, float* __restrict__ out) {
    __shared__ float eGA_s[Kn*Hn];
    __shared__ float eGB_s[Kn*Wn];
    __shared__ int r_s;
    int nb = blockIdx.y;
    int n = nb >> 2, b = nb & 3;
    if (threadIdx.x == 0) {
        int my = (int)rois[n*5];
        int r = 0;
        #pragma unroll
        for (int j = 0; j < Nn; ++j) {
            int o = (int)rois[j*5];
            r += (o < my) || (o == my && j < n);
        }
        r_s = r;
    }
    for (int i = threadIdx.x; i < Kn*Hn; i += 256) eGA_s[i] = g_eGA[n*Kn*Hn + i];
    for (int i = threadIdx.x; i < Kn*Wn; i += 256) eGB_s[i] = g_eGB[n*Kn*Wn + i];
    __syncthreads();
    int p = (blockIdx.x*256 + threadIdx.x) * 4;
    int h = p / 48;
    int w = p - h*48;
    const float* ea = g_eapp + (size_t)b*Kn*HWn + p;
    float s0 = 0.f, s1 = 0.f, s2 = 0.f, s3 = 0.f;
    #pragma unroll
    for (int k = 0; k < Kn; ++k) {
        float  ga = eGA_s[k*Hn + h];
        float4 gb = *(const float4*)(eGB_s + k*Wn + w);
        float4 ev = *(const float4*)(ea + (size_t)k*HWn);
        s0 += ga * gb.x * ev.x;
        s1 += ga * gb.y * ev.y;
        s2 += ga * gb.z * ev.z;
        s3 += ga * gb.w * ev.w;
    }
    float i0 = 1.0f/s0, i1 = 1.0f/s1, i2 = 1.0f/s2, i3 = 1.0f/s3;
    float* op = out + ((size_t)(r_s*Bn + b)*Kn)*HWn + p;
    #pragma unroll
    for (int k = 0; k < Kn; ++k) {
        float  ga = eGA_s[k*Hn + h];
        float4 gb = *(const float4*)(eGB_s + k*Wn + w);
        float4 ev = *(const float4*)(ea + (size_t)k*HWn);
        float4 v;
        v.x = ga * gb.x * ev.x * i0;
        v.y = ga * gb.y * ev.y * i1;
        v.z = ga * gb.z * ev.z * i2;
        v.w = ga * gb.w * ev.w * i3;
        *(float4*)(op + (size_t)k*HWn) = v;
    }
}

extern "C" void kernel_launch(void* const* d_in, const int* in_sizes, int n_in,
                              void* d_out, int out_size) {
    const float* x      = (const float*)d_in[0];
    const float* rois   = (const float*)d_in[1];
    const float* V_box  = (const float*)d_in[2];
    const float* W_box  = (const float*)d_in[3];
    const float* W_im   = (const float*)d_in[4];
    const float* conv_w = (const float*)d_in[5];
    const float* conv_b = (const float*)d_in[6];
    float* out = (float*)d_out;

    int smem_vapp = (52*256 + 64*34) * 4;    // 62 KB (app role is max)
    int smem_bvec = (32*128 + 64*130) * 4;   // 49.7 KB
    int smem_gab  = (2*32*GST) * 4;          // 66.6 KB
    cudaFuncSetAttribute(k_vapp, cudaFuncAttributeMaxDynamicSharedMemorySize, smem_vapp);
    cudaFuncSetAttribute(k_bvec, cudaFuncAttributeMaxDynamicSharedMemorySize, smem_bvec);
    cudaFuncSetAttribute(k_GAB,  cudaFuncAttributeMaxDynamicSharedMemorySize, smem_gab);

    k_pre  <<<Nn + 16 + 2 + 16, 256>>>(rois, W_im);
    k_vapp <<<256 + 192, 256, smem_vapp>>>(V_box, x, conv_w, conv_b);
    k_bvec <<<dim3(KOn/64, BSPLIT), 256, smem_bvec>>>(W_box);
    k_GAB  <<<dim3(Nn, 2, 4), 256, smem_gab>>>();
    k_final<<<dim3(HWn/1024, Nn*Bn), 256>>>(rois, out);
}

// round 12
// speedup vs baseline: 1.2670x; 1.2670x over previous
#include <cuda_runtime.h>
#include <math.h>

#define Dn   512
#define FDn  2048
#define On   256
#define Kn   49
#define Bn   4
#define Cn   256
#define Hn   64
#define Wn   48
#define HWn  3072
#define Nn   32
#define KOn  (Kn*On)     // 12544
#define KOP  16384       // padded 64*256
#define BSPLIT 4
#define GST  260         // k_GAB smem row stride

typedef unsigned long long u64;

__device__ float g_eps [Nn*FDn];
__device__ float g_pe  [Hn*Dn];           // embed table, rows 0..63 (B uses 0..47)
__device__ float g_v   [Nn*Dn];
__device__ float g_bvec[Nn*KOP];          // k padded to 64; slots >=49*256 stay 0
__device__ float g_A   [Hn*On];
__device__ float g_Bm  [Wn*On];
__device__ float g_eGA [Nn*Kn*Hn];
__device__ float g_eGB [Nn*Kn*Wn];
__device__ float g_eapp[Bn*Kn*HWn];

__device__ __forceinline__ void ffma2(u64 &acc, u64 a, u64 b) {
    asm volatile("fma.rn.f32x2 %0, %1, %2, %0;" : "+l"(acc) : "l"(a), "l"(b));
}
__device__ __forceinline__ float hsum2(u64 a) {
    float2 f = *reinterpret_cast<float2*>(&a);
    return f.x + f.y;
}

__device__ __forceinline__ float embed_val(float z, int dd) {
    float e = (dd < 256) ? (2.0f*dd + 1.0f)*(1.0f/512.0f) : (2.0f*(dd-256))*(1.0f/512.0f);
    float invden = exp2f(-e * 9.96578428466209f);   // 1000^-e
    double a = (double)z * (double)invden;
    double k = rint(a * 0.15915494309189535);
    float  r = (float)(a - k * 6.2831853071795864769);
    return (dd < 256) ? sinf(r) : cosf(r);
}

// blocks: 0..31 eps | 32,33 pe table | 34,35 zero g_v | 36..51 zero g_bvec
__global__ void k_pre(const float* __restrict__ rois) {
    int bid = blockIdx.x;
    if (bid < Nn) {
        int n = bid;
        float c0 = rois[n*5+1], c1 = rois[n*5+2], c2 = rois[n*5+3], c3 = rois[n*5+4];
        for (int i = threadIdx.x; i < FDn; i += blockDim.x) {
            int c  = i >> 9;
            int dd = i & 511;
            float z = (c >= 2) ? ((c == 3) ? c3 : c2) : ((c == 1) ? c1 : c0);
            g_eps[n*FDn + i] = embed_val(z, dd);
        }
    } else if (bid < Nn + 2) {
        int half = bid - Nn;                    // j range [half*32, half*32+32)
        int base = half * 32 * Dn;
        for (int i = threadIdx.x; i < 32*Dn; i += 256) {
            int j = i >> 9, dd = i & 511;
            g_pe[base + i] = embed_val((float)(half*32 + j), dd);
        }
    } else if (bid < Nn + 4) {
        int half = bid - (Nn + 2);
        int base = half * (Nn*Dn/2);
        for (int i = threadIdx.x; i < Nn*Dn/2; i += 256)
            g_v[base + i] = 0.0f;
    } else {
        int seg = bid - (Nn + 4);     // 0..15
        int base = seg * (Nn*KOP/16);
        for (int i = threadIdx.x; i < Nn*KOP/16; i += 256)
            g_bvec[base + i] = 0.0f;
    }
}

// ===== fused: v (0..255) | app (256..447) | A/B GEMM (448..463) ================
__global__ void k_vapp(const float* __restrict__ V_box,
                       const float* __restrict__ x,
                       const float* __restrict__ conv_w,
                       const float* __restrict__ conv_b,
                       const float* __restrict__ W_im) {
    extern __shared__ __align__(16) float sm[];
    int bx = blockIdx.x;
    if (bx < 256) {
        // ---------------- v role ----------------
        float* eps_s = sm;             // [32 n][128 f]
        float* vt_s  = sm + 32*128;    // [32 d][130]
        int dp = bx >> 4, ks = bx & 15;
        int f0 = ks * 128;
        for (int i = threadIdx.x; i < 32*128; i += 256) {
            int n = i >> 7, f = i & 127;
            eps_s[i] = g_eps[n*FDn + f0 + f];
        }
        int srow = threadIdx.x >> 5, scol = threadIdx.x & 31;
        #pragma unroll
        for (int p = 0; p < 4; ++p) {
            int row = p*8 + srow;
            float4 vv = *(const float4*)(V_box + (size_t)(dp*32 + row)*FDn + f0 + scol*4);
            float* dst = vt_s + row*130 + scol*4;
            *(float2*)(dst)     = make_float2(vv.x, vv.y);
            *(float2*)(dst + 2) = make_float2(vv.z, vv.w);
        }
        __syncthreads();
        int dl = threadIdx.x & 31, ng = threadIdx.x >> 5;
        int d  = dp*32 + dl, n0 = ng*4;
        u64 acc[4] = {0,0,0,0};
        const float* vrow = vt_s + dl*130;
        #pragma unroll 8
        for (int fq = 0; fq < 32; ++fq) {
            u64 w0 = *(const u64*)(vrow + fq*4);
            u64 w1 = *(const u64*)(vrow + fq*4 + 2);
            #pragma unroll
            for (int j = 0; j < 4; ++j) {
                ulonglong2 ev = *(const ulonglong2*)(eps_s + (n0+j)*128 + fq*4);
                ffma2(acc[j], w0, ev.x);
                ffma2(acc[j], w1, ev.y);
            }
        }
        #pragma unroll
        for (int j = 0; j < 4; ++j)
            atomicAdd(&g_v[(size_t)(n0+j)*Dn + d], hsum2(acc[j]));
    } else if (bx < 448) {
        // ---------------- app role: smem weights, 2 px/thread, 7 k/group -------
        float* cw_s = sm;              // 56 x 256
        float* x_s  = sm + 56*256;     // 64 c x 64 p
        int r   = bx - 256;
        int b   = r / 48;
        int px0 = (r - b*48) * 64;
        for (int i = threadIdx.x; i < 56*256; i += 256) {
            int k = i >> 8, c = i & 255;
            cw_s[i] = (k < Kn) ? conv_w[k*Cn + c] : 0.0f;
        }
        int lane = threadIdx.x & 31;
        int kg   = threadIdx.x >> 5;
        int k0   = kg * 7;
        u64 acc[7];
        #pragma unroll
        for (int kk = 0; kk < 7; ++kk) acc[kk] = 0;

        for (int c0 = 0; c0 < Cn; c0 += 64) {
            __syncthreads();
            for (int i = threadIdx.x; i < 64*64; i += 256) {
                int c = i >> 6, p = i & 63;
                x_s[i] = x[((size_t)b*Cn + c0 + c)*HWn + px0 + p];
            }
            __syncthreads();
            #pragma unroll 4
            for (int c = 0; c < 64; ++c) {
                u64 xv = *(const u64*)(x_s + c*64 + lane*2);
                #pragma unroll
                for (int kk = 0; kk < 7; ++kk) {
                    float w = cw_s[(k0+kk)*256 + c0 + c];
                    u64 w2; asm("mov.b64 %0, {%1, %1};" : "=l"(w2) : "f"(w));
                    ffma2(acc[kk], w2, xv);
                }
            }
        }
        int p0 = px0 + lane*2;
        #pragma unroll
        for (int kk = 0; kk < 7; ++kk) {
            int k = k0 + kk;
            if (k < Kn) {
                float bias = conv_b[k];
                float2 a0 = *(float2*)&acc[kk];
                float2 v;
                v.x = expf(a0.x + bias);
                v.y = expf(a0.y + bias);
                *(float2*)(g_eapp + ((size_t)b*Kn + k)*HWn + p0) = v;
            }
        }
    } else {
        // ------- A/B role: out[j,o] = sum_f pe[j,f] * W_im[o, side*512+f] ------
        float* pe_s = sm;              // [64 j][130]
        float* w_s  = sm + 64*130;     // [32 o][130]
        int t    = bx - 448;           // 0..15
        int side = t >> 3;             // 0=A, 1=B
        int o0   = (t & 7) * 32;
        int ol = threadIdx.x & 31, jg = threadIdx.x >> 5;
        u64 acc[8] = {0,0,0,0,0,0,0,0};
        for (int fs = 0; fs < 4; ++fs) {
            int f0 = fs * 128;
            __syncthreads();
            for (int i = threadIdx.x; i < 64*128; i += 256) {
                int j = i >> 7, fl = i & 127;
                pe_s[j*130 + fl] = g_pe[j*Dn + f0 + fl];
            }
            {
                int srow = threadIdx.x >> 5, scol = threadIdx.x & 31;
                #pragma unroll
                for (int p = 0; p < 4; ++p) {
                    int row = p*8 + srow;
                    float4 wv = *(const float4*)(W_im + (size_t)(o0 + row)*(2*Dn)
                                                 + side*Dn + f0 + scol*4);
                    float* dst = w_s + row*130 + scol*4;
                    *(float2*)(dst)     = make_float2(wv.x, wv.y);
                    *(float2*)(dst + 2) = make_float2(wv.z, wv.w);
                }
            }
            __syncthreads();
            const float* wrow = w_s + ol*130;
            #pragma unroll 4
            for (int fq = 0; fq < 32; ++fq) {
                u64 w0 = *(const u64*)(wrow + fq*4);
                u64 w1 = *(const u64*)(wrow + fq*4 + 2);
                #pragma unroll
                for (int jj = 0; jj < 8; ++jj) {
                    const float* pr = pe_s + (jg*8 + jj)*130 + fq*4;
                    ffma2(acc[jj], w0, *(const u64*)pr);
                    ffma2(acc[jj], w1, *(const u64*)(pr + 2));
                }
            }
        }
        int o = o0 + ol;
        #pragma unroll
        for (int jj = 0; jj < 8; ++jj) {
            int j = jg*8 + jj;
            if (side == 0) g_A[j*On + o] = hsum2(acc[jj]);
            else if (j < Wn) g_Bm[j*On + o] = hsum2(acc[jj]);
        }
    }
}

// ---------------- bvec: grid (196 ko-tiles, 4 d-slices), atomic reduce ----------
__global__ void k_bvec(const float* __restrict__ W_box) {
    extern __shared__ __align__(16) float smb[];
    float* v_s  = smb;            // [32 n][128 f]
    float* wt_s = smb + 32*128;   // [64 ko][130]
    int ks = blockIdx.y;
    int f0 = ks * 128;
    int ko0 = blockIdx.x * 64;
    for (int i = threadIdx.x; i < 32*128; i += 256) {
        int n = i >> 7, fl = i & 127;
        v_s[i] = g_v[n*Dn + f0 + fl];
    }
    int srow = threadIdx.x >> 5, scol = threadIdx.x & 31;
    #pragma unroll
    for (int p = 0; p < 8; ++p) {
        int row = p*8 + srow;
        float4 wv = *(const float4*)(W_box + (size_t)(ko0 + row)*Dn + f0 + scol*4);
        float* dst = wt_s + row*130 + scol*4;
        *(float2*)(dst)     = make_float2(wv.x, wv.y);
        *(float2*)(dst + 2) = make_float2(wv.z, wv.w);
    }
    __syncthreads();
    int kol = threadIdx.x & 63;
    int ng  = threadIdx.x >> 6;
    int n0  = ng * 8;
    int ko  = ko0 + kol;
    int k   = ko >> 8, o = ko & 255;
    const float* wrow = wt_s + kol*130;
    u64 acc[8] = {0,0,0,0,0,0,0,0};
    #pragma unroll 4
    for (int fq = 0; fq < 32; ++fq) {
        u64 w0 = *(const u64*)(wrow + fq*4);
        u64 w1 = *(const u64*)(wrow + fq*4 + 2);
        #pragma unroll
        for (int j = 0; j < 8; ++j) {
            ulonglong2 vv = *(const ulonglong2*)(v_s + (n0+j)*128 + fq*4);
            ffma2(acc[j], w0, vv.x);
            ffma2(acc[j], w1, vv.y);
        }
    }
    #pragma unroll
    for (int j = 0; j < 8; ++j)
        atomicAdd(&g_bvec[(size_t)(n0+j)*KOP + k*256 + o], hsum2(acc[j]));
}

// -------- eGA/eGB: register-tiled GEMM, grid (n, side, lz*2+kz) ----------------
__global__ void k_GAB() {
    extern __shared__ __align__(16) float smg[];
    float* M_s  = smg;             // 32*GST
    float* bv_s = smg + 32*GST;    // 32*GST
    int n  = blockIdx.x;
    bool isA = (blockIdx.y == 0);
    int lz = blockIdx.z >> 1, kz = blockIdx.z & 1;
    int L    = isA ? Hn : Wn;
    int rows = isA ? 32 : 24;
    int loff = lz * rows;
    int k0   = kz * 32;
    const float* src = isA ? g_A : g_Bm;
    for (int i = threadIdx.x; i < rows*64; i += 256) {
        int r = i >> 6, o4 = i & 63;
        *(float4*)(M_s + r*GST + o4*4) =
            *(const float4*)(src + (size_t)(loff + r)*On + o4*4);
    }
    for (int i = threadIdx.x; i < 32*64; i += 256) {
        int r = i >> 6, o4 = i & 63;
        *(float4*)(bv_s + r*GST + o4*4) =
            *(const float4*)(g_bvec + (size_t)n*KOP + (size_t)(k0 + r)*On + o4*4);
    }
    __syncthreads();
    int lq = threadIdx.x & 15, kq = threadIdx.x >> 4;
    const float* m0 = M_s + lq*GST;
    const float* m1 = M_s + (lq + 16)*GST;
    const float* b0 = bv_s + (kq*2)*GST;
    const float* b1 = b0 + GST;
    float a00=0.f, a01=0.f, a10=0.f, a11=0.f;
    #pragma unroll 4
    for (int o4 = 0; o4 < 64; ++o4) {
        float4 ma = *(const float4*)(m0 + o4*4);
        float4 mb = *(const float4*)(m1 + o4*4);
        float4 ba = *(const float4*)(b0 + o4*4);
        float4 bb = *(const float4*)(b1 + o4*4);
        a00 += ma.x*ba.x + ma.y*ba.y + ma.z*ba.z + ma.w*ba.w;
        a01 += ma.x*bb.x + ma.y*bb.y + ma.z*bb.z + ma.w*bb.w;
        a10 += mb.x*ba.x + mb.y*ba.y + mb.z*ba.z + mb.w*ba.w;
        a11 += mb.x*bb.x + mb.y*bb.y + mb.z*bb.z + mb.w*bb.w;
    }
    int l0 = loff + lq;
    int l1 = loff + lq + 16;
    int k  = k0 + kq*2;
    bool l1ok = (lq + 16) < rows;
    float* dst = isA ? (g_eGA + (size_t)n*Kn*Hn) : (g_eGB + (size_t)n*Kn*Wn);
    if (k < Kn) {
        dst[k*L + l0] = expf(a00);
        if (l1ok) dst[k*L + l1] = expf(a10);
    }
    if (k + 1 < Kn) {
        dst[(k+1)*L + l0] = expf(a01);
        if (l1ok) dst[(k+1)*L + l1] = expf(a11);
    }
}

// ---------------- final: 4 px/thread, float4 I/O, softmax over k ----------------
__global__ void k_final(const float* __restrict__ rois, float* __restrict__ out) {
    __shared__ float eGA_s[Kn*Hn];
    __shared__ float eGB_s[Kn*Wn];
    __shared__ int r_s;
    int nb = blockIdx.y;
    int n = nb >> 2, b = nb & 3;
    if (threadIdx.x == 0) {
        int my = (int)rois[n*5];
        int r = 0;
        #pragma unroll
        for (int j = 0; j < Nn; ++j) {
            int o = (int)rois[j*5];
            r += (o < my) || (o == my && j < n);
        }
        r_s = r;
    }
    for (int i = threadIdx.x; i < Kn*Hn; i += 256) eGA_s[i] = g_eGA[n*Kn*Hn + i];
    for (int i = threadIdx.x; i < Kn*Wn; i += 256) eGB_s[i] = g_eGB[n*Kn*Wn + i];
    __syncthreads();
    int p = (blockIdx.x*256 + threadIdx.x) * 4;
    int h = p / 48;
    int w = p - h*48;
    const float* ea = g_eapp + (size_t)b*Kn*HWn + p;
    float s0 = 0.f, s1 = 0.f, s2 = 0.f, s3 = 0.f;
    #pragma unroll
    for (int k = 0; k < Kn; ++k) {
        float  ga = eGA_s[k*Hn + h];
        float4 gb = *(const float4*)(eGB_s + k*Wn + w);
        float4 ev = *(const float4*)(ea + (size_t)k*HWn);
        s0 += ga * gb.x * ev.x;
        s1 += ga * gb.y * ev.y;
        s2 += ga * gb.z * ev.z;
        s3 += ga * gb.w * ev.w;
    }
    float i0 = 1.0f/s0, i1 = 1.0f/s1, i2 = 1.0f/s2, i3 = 1.0f/s3;
    float* op = out + ((size_t)(r_s*Bn + b)*Kn)*HWn + p;
    #pragma unroll
    for (int k = 0; k < Kn; ++k) {
        float  ga = eGA_s[k*Hn + h];
        float4 gb = *(const float4*)(eGB_s + k*Wn + w);
        float4 ev = *(const float4*)(ea + (size_t)k*HWn);
        float4 v;
        v.x = ga * gb.x * ev.x * i0;
        v.y = ga * gb.y * ev.y * i1;
        v.z = ga * gb.z * ev.z * i2;
        v.w = ga * gb.w * ev.w * i3;
        *(float4*)(op + (size_t)k*HWn) = v;
    }
}

extern "C" void kernel_launch(void* const* d_in, const int* in_sizes, int n_in,
                              void* d_out, int out_size) {
    const float* x      = (const float*)d_in[0];
    const float* rois   = (const float*)d_in[1];
    const float* V_box  = (const float*)d_in[2];
    const float* W_box  = (const float*)d_in[3];
    const float* W_im   = (const float*)d_in[4];
    const float* conv_w = (const float*)d_in[5];
    const float* conv_b = (const float*)d_in[6];
    float* out = (float*)d_out;

    int smem_vapp = (56*256 + 64*64) * 4;    // 73.7 KB (app role is max)
    int smem_bvec = (32*128 + 64*130) * 4;   // 49.7 KB
    int smem_gab  = (2*32*GST) * 4;          // 66.6 KB
    cudaFuncSetAttribute(k_vapp, cudaFuncAttributeMaxDynamicSharedMemorySize, smem_vapp);
    cudaFuncSetAttribute(k_bvec, cudaFuncAttributeMaxDynamicSharedMemorySize, smem_bvec);
    cudaFuncSetAttribute(k_GAB,  cudaFuncAttributeMaxDynamicSharedMemorySize, smem_gab);

    k_pre  <<<Nn + 2 + 2 + 16, 256>>>(rois);
    k_vapp <<<256 + 192 + 16, 256, smem_vapp>>>(V_box, x, conv_w, conv_b, W_im);
    k_bvec <<<dim3(KOn/64, BSPLIT), 256, smem_bvec>>>(W_box);
    k_GAB  <<<dim3(Nn, 2, 4), 256, smem_gab>>>();
    k_final<<<dim3(HWn/1024, Nn*Bn), 256>>>(rois, out);
}

// round 13
// speedup vs baseline: 1.4133x; 1.1154x over previous
#include <cuda_runtime.h>
#include <math.h>

#define Dn   512
#define FDn  2048
#define On   256
#define Kn   49
#define Bn   4
#define Cn   256
#define Hn   64
#define Wn   48
#define HWn  3072
#define Nn   32
#define KOn  (Kn*On)     // 12544
#define KOP  16384       // padded 64*256
#define BSPLIT 4
#define GST  260         // k_GAB smem row stride
#define WST  34          // k_pre W_im smem row stride (32 + 2 pad)

typedef unsigned long long u64;

__device__ float g_eps [Nn*FDn];
__device__ float g_v   [Nn*Dn];
__device__ float g_bvec[Nn*KOP];          // k padded to 64; slots >=49*256 stay 0
__device__ float g_A   [Hn*On];
__device__ float g_Bm  [Wn*On];
__device__ float g_eGA [Nn*Kn*Hn];
__device__ float g_eGB [Nn*Kn*Wn];
__device__ float g_eapp[Bn*Kn*HWn];

__device__ __forceinline__ void ffma2(u64 &acc, u64 a, u64 b) {
    asm volatile("fma.rn.f32x2 %0, %1, %2, %0;" : "+l"(acc) : "l"(a), "l"(b));
}
__device__ __forceinline__ float hsum2(u64 a) {
    float2 f = *reinterpret_cast<float2*>(&a);
    return f.x + f.y;
}

__device__ __forceinline__ float embed_val(float z, int dd) {
    float e = (dd < 256) ? (2.0f*dd + 1.0f)*(1.0f/512.0f) : (2.0f*(dd-256))*(1.0f/512.0f);
    float invden = exp2f(-e * 9.96578428466209f);   // 1000^-e
    double a = (double)z * (double)invden;
    double k = rint(a * 0.15915494309189535);
    float  r = (float)(a - k * 6.2831853071795864769);
    return (dd < 256) ? sinf(r) : cosf(r);
}

// blocks: 0..31 eps | 32..143 A/B (smem-staged W_im) | 144,145 zero g_v | 146..161 zero g_bvec
__global__ void k_pre(const float* __restrict__ rois,
                      const float* __restrict__ W_im) {
    __shared__ __align__(16) float pe[Dn];
    __shared__ __align__(8)  float ws[256*WST];   // [256 o][32 f chunk], 34.8 KB
    int bid = blockIdx.x;
    if (bid < Nn) {
        int n = bid;
        float c0 = rois[n*5+1], c1 = rois[n*5+2], c2 = rois[n*5+3], c3 = rois[n*5+4];
        for (int i = threadIdx.x; i < FDn; i += blockDim.x) {
            int c  = i >> 9;
            int dd = i & 511;
            float z = (c >= 2) ? ((c == 3) ? c3 : c2) : ((c == 1) ? c1 : c0);
            g_eps[n*FDn + i] = embed_val(z, dd);
        }
    } else if (bid < Nn + Hn + Wn) {
        int j = bid - Nn;
        bool isA = (j < Hn);
        float z = (float)(isA ? j : (j - Hn));
        for (int dd = threadIdx.x; dd < Dn; dd += blockDim.x)
            pe[dd] = embed_val(z, dd);
        int o = threadIdx.x;
        const float* wbase = W_im + (isA ? 0 : Dn);
        u64 acc = 0;
        for (int ch = 0; ch < 16; ++ch) {
            int f0 = ch * 32;
            __syncthreads();
            // stage W_im[:, f0:f0+32] coalesced: warp-LDG covers 4 rows x 128B
            #pragma unroll
            for (int q = 0; q < 8; ++q) {
                int idx = q*256 + threadIdx.x;    // float4 units, 0..2047
                int oo = idx >> 3, f4 = idx & 7;
                float4 wv = *(const float4*)(wbase + (size_t)oo*(2*Dn) + f0 + f4*4);
                float* dst = ws + oo*WST + f4*4;
                *(float2*)(dst)     = make_float2(wv.x, wv.y);
                *(float2*)(dst + 2) = make_float2(wv.z, wv.w);
            }
            __syncthreads();
            const float* wr = ws + o*WST;
            const float* pr = pe + f0;
            #pragma unroll
            for (int t = 0; t < 8; ++t) {
                u64 w0 = *(const u64*)(wr + t*4);
                u64 w1 = *(const u64*)(wr + t*4 + 2);
                ffma2(acc, w0, *(const u64*)(pr + t*4));
                ffma2(acc, w1, *(const u64*)(pr + t*4 + 2));
            }
        }
        if (isA) g_A[j*On + o] = hsum2(acc);
        else     g_Bm[(j-Hn)*On + o] = hsum2(acc);
    } else if (bid < Nn + Hn + Wn + 2) {
        int half = bid - (Nn + Hn + Wn);
        int base = half * (Nn*Dn/2);
        for (int i = threadIdx.x; i < Nn*Dn/2; i += 256)
            g_v[base + i] = 0.0f;
    } else {
        int seg = bid - (Nn + Hn + Wn + 2);     // 0..15
        int base = seg * (Nn*KOP/16);
        for (int i = threadIdx.x; i < Nn*KOP/16; i += 256)
            g_bvec[base + i] = 0.0f;
    }
}

// ================= fused v (blocks 0..255) + app (blocks 256..447) =============
__global__ void k_vapp(const float* __restrict__ V_box,
                       const float* __restrict__ x,
                       const float* __restrict__ conv_w,
                       const float* __restrict__ conv_b) {
    extern __shared__ __align__(16) float sm[];
    int bx = blockIdx.x;
    if (bx < 256) {
        // ---------------- v role ----------------
        float* eps_s = sm;             // [32 n][128 f]
        float* vt_s  = sm + 32*128;    // [32 d][130]
        int dp = bx >> 4, ks = bx & 15;
        int f0 = ks * 128;
        for (int i = threadIdx.x; i < 32*128; i += 256) {
            int n = i >> 7, f = i & 127;
            eps_s[i] = g_eps[n*FDn + f0 + f];
        }
        int srow = threadIdx.x >> 5, scol = threadIdx.x & 31;
        #pragma unroll
        for (int p = 0; p < 4; ++p) {
            int row = p*8 + srow;
            float4 vv = *(const float4*)(V_box + (size_t)(dp*32 + row)*FDn + f0 + scol*4);
            float* dst = vt_s + row*130 + scol*4;
            *(float2*)(dst)     = make_float2(vv.x, vv.y);
            *(float2*)(dst + 2) = make_float2(vv.z, vv.w);
        }
        __syncthreads();
        int dl = threadIdx.x & 31, ng = threadIdx.x >> 5;
        int d  = dp*32 + dl, n0 = ng*4;
        u64 acc[4] = {0,0,0,0};
        const float* vrow = vt_s + dl*130;
        #pragma unroll 8
        for (int fq = 0; fq < 32; ++fq) {
            u64 w0 = *(const u64*)(vrow + fq*4);
            u64 w1 = *(const u64*)(vrow + fq*4 + 2);
            #pragma unroll
            for (int j = 0; j < 4; ++j) {
                ulonglong2 ev = *(const ulonglong2*)(eps_s + (n0+j)*128 + fq*4);
                ffma2(acc[j], w0, ev.x);
                ffma2(acc[j], w1, ev.y);
            }
        }
        #pragma unroll
        for (int j = 0; j < 4; ++j)
            atomicAdd(&g_v[(size_t)(n0+j)*Dn + d], hsum2(acc[j]));
    } else {
        // ---------------- app role: smem weights, 2 px/thread, 7 k/group -------
        float* cw_s = sm;              // 56 x 256
        float* x_s  = sm + 56*256;     // 64 c x 64 p
        int r   = bx - 256;
        int b   = r / 48;
        int px0 = (r - b*48) * 64;
        for (int i = threadIdx.x; i < 56*256; i += 256) {
            int k = i >> 8, c = i & 255;
            cw_s[i] = (k < Kn) ? conv_w[k*Cn + c] : 0.0f;
        }
        int lane = threadIdx.x & 31;
        int kg   = threadIdx.x >> 5;
        int k0   = kg * 7;
        u64 acc[7];
        #pragma unroll
        for (int kk = 0; kk < 7; ++kk) acc[kk] = 0;

        for (int c0 = 0; c0 < Cn; c0 += 64) {
            __syncthreads();
            for (int i = threadIdx.x; i < 64*64; i += 256) {
                int c = i >> 6, p = i & 63;
                x_s[i] = x[((size_t)b*Cn + c0 + c)*HWn + px0 + p];
            }
            __syncthreads();
            #pragma unroll 4
            for (int c = 0; c < 64; ++c) {
                u64 xv = *(const u64*)(x_s + c*64 + lane*2);
                #pragma unroll
                for (int kk = 0; kk < 7; ++kk) {
                    float w = cw_s[(k0+kk)*256 + c0 + c];
                    u64 w2; asm("mov.b64 %0, {%1, %1};" : "=l"(w2) : "f"(w));
                    ffma2(acc[kk], w2, xv);
                }
            }
        }
        int p0 = px0 + lane*2;
        #pragma unroll
        for (int kk = 0; kk < 7; ++kk) {
            int k = k0 + kk;
            if (k < Kn) {
                float bias = conv_b[k];
                float2 a0 = *(float2*)&acc[kk];
                float2 v;
                v.x = expf(a0.x + bias);
                v.y = expf(a0.y + bias);
                *(float2*)(g_eapp + ((size_t)b*Kn + k)*HWn + p0) = v;
            }
        }
    }
}

// ---------------- bvec: grid (196 ko-tiles, 4 d-slices), atomic reduce ----------
__global__ void k_bvec(const float* __restrict__ W_box) {
    extern __shared__ __align__(16) float smb[];
    float* v_s  = smb;            // [32 n][128 f]
    float* wt_s = smb + 32*128;   // [64 ko][130]
    int ks = blockIdx.y;
    int f0 = ks * 128;
    int ko0 = blockIdx.x * 64;
    for (int i = threadIdx.x; i < 32*128; i += 256) {
        int n = i >> 7, fl = i & 127;
        v_s[i] = g_v[n*Dn + f0 + fl];
    }
    int srow = threadIdx.x >> 5, scol = threadIdx.x & 31;
    #pragma unroll
    for (int p = 0; p < 8; ++p) {
        int row = p*8 + srow;
        float4 wv = *(const float4*)(W_box + (size_t)(ko0 + row)*Dn + f0 + scol*4);
        float* dst = wt_s + row*130 + scol*4;
        *(float2*)(dst)     = make_float2(wv.x, wv.y);
        *(float2*)(dst + 2) = make_float2(wv.z, wv.w);
    }
    __syncthreads();
    int kol = threadIdx.x & 63;
    int ng  = threadIdx.x >> 6;
    int n0  = ng * 8;
    int ko  = ko0 + kol;
    int k   = ko >> 8, o = ko & 255;
    const float* wrow = wt_s + kol*130;
    u64 acc[8] = {0,0,0,0,0,0,0,0};
    #pragma unroll 4
    for (int fq = 0; fq < 32; ++fq) {
        u64 w0 = *(const u64*)(wrow + fq*4);
        u64 w1 = *(const u64*)(wrow + fq*4 + 2);
        #pragma unroll
        for (int j = 0; j < 8; ++j) {
            ulonglong2 vv = *(const ulonglong2*)(v_s + (n0+j)*128 + fq*4);
            ffma2(acc[j], w0, vv.x);
            ffma2(acc[j], w1, vv.y);
        }
    }
    #pragma unroll
    for (int j = 0; j < 8; ++j)
        atomicAdd(&g_bvec[(size_t)(n0+j)*KOP + k*256 + o], hsum2(acc[j]));
}

// -------- eGA/eGB: register-tiled GEMM, grid (n, side, lz*2+kz) ----------------
__global__ void k_GAB() {
    extern __shared__ __align__(16) float smg[];
    float* M_s  = smg;             // 32*GST
    float* bv_s = smg + 32*GST;    // 32*GST
    int n  = blockIdx.x;
    bool isA = (blockIdx.y == 0);
    int lz = blockIdx.z >> 1, kz = blockIdx.z & 1;
    int L    = isA ? Hn : Wn;
    int rows = isA ? 32 : 24;
    int loff = lz * rows;
    int k0   = kz * 32;
    const float* src = isA ? g_A : g_Bm;
    for (int i = threadIdx.x; i < rows*64; i += 256) {
        int r = i >> 6, o4 = i & 63;
        *(float4*)(M_s + r*GST + o4*4) =
            *(const float4*)(src + (size_t)(loff + r)*On + o4*4);
    }
    for (int i = threadIdx.x; i < 32*64; i += 256) {
        int r = i >> 6, o4 = i & 63;
        *(float4*)(bv_s + r*GST + o4*4) =
            *(const float4*)(g_bvec + (size_t)n*KOP + (size_t)(k0 + r)*On + o4*4);
    }
    __syncthreads();
    int lq = threadIdx.x & 15, kq = threadIdx.x >> 4;
    const float* m0 = M_s + lq*GST;
    const float* m1 = M_s + (lq + 16)*GST;
    const float* b0 = bv_s + (kq*2)*GST;
    const float* b1 = b0 + GST;
    float a00=0.f, a01=0.f, a10=0.f, a11=0.f;
    #pragma unroll 4
    for (int o4 = 0; o4 < 64; ++o4) {
        float4 ma = *(const float4*)(m0 + o4*4);
        float4 mb = *(const float4*)(m1 + o4*4);
        float4 ba = *(const float4*)(b0 + o4*4);
        float4 bb = *(const float4*)(b1 + o4*4);
        a00 += ma.x*ba.x + ma.y*ba.y + ma.z*ba.z + ma.w*ba.w;
        a01 += ma.x*bb.x + ma.y*bb.y + ma.z*bb.z + ma.w*bb.w;
        a10 += mb.x*ba.x + mb.y*ba.y + mb.z*ba.z + mb.w*ba.w;
        a11 += mb.x*bb.x + mb.y*bb.y + mb.z*bb.z + mb.w*bb.w;
    }
    int l0 = loff + lq;
    int l1 = loff + lq + 16;
    int k  = k0 + kq*2;
    bool l1ok = (lq + 16) < rows;
    float* dst = isA ? (g_eGA + (size_t)n*Kn*Hn) : (g_eGB + (size_t)n*Kn*Wn);
    if (k < Kn) {
        dst[k*L + l0] = expf(a00);
        if (l1ok) dst[k*L + l1] = expf(a10);
    }
    if (k + 1 < Kn) {
        dst[(k+1)*L + l0] = expf(a01);
        if (l1ok) dst[(k+1)*L + l1] = expf(a11);
    }
}

// ---------------- final: 4 px/thread, float4 I/O, softmax over k ----------------
__global__ void k_final(const float* __restrict__ rois, float* __restrict__ out) {
    __shared__ float eGA_s[Kn*Hn];
    __shared__ float eGB_s[Kn*Wn];
    __shared__ int r_s;
    int nb = blockIdx.y;
    int n = nb >> 2, b = nb & 3;
    if (threadIdx.x == 0) {
        int my = (int)rois[n*5];
        int r = 0;
        #pragma unroll
        for (int j = 0; j < Nn; ++j) {
            int o = (int)rois[j*5];
            r += (o < my) || (o == my && j < n);
        }
        r_s = r;
    }
    for (int i = threadIdx.x; i < Kn*Hn; i += 256) eGA_s[i] = g_eGA[n*Kn*Hn + i];
    for (int i = threadIdx.x; i < Kn*Wn; i += 256) eGB_s[i] = g_eGB[n*Kn*Wn + i];
    __syncthreads();
    int p = (blockIdx.x*256 + threadIdx.x) * 4;
    int h = p / 48;
    int w = p - h*48;
    const float* ea = g_eapp + (size_t)b*Kn*HWn + p;
    float s0 = 0.f, s1 = 0.f, s2 = 0.f, s3 = 0.f;
    #pragma unroll
    for (int k = 0; k < Kn; ++k) {
        float  ga = eGA_s[k*Hn + h];
        float4 gb = *(const float4*)(eGB_s + k*Wn + w);
        float4 ev = *(const float4*)(ea + (size_t)k*HWn);
        s0 += ga * gb.x * ev.x;
        s1 += ga * gb.y * ev.y;
        s2 += ga * gb.z * ev.z;
        s3 += ga * gb.w * ev.w;
    }
    float i0 = 1.0f/s0, i1 = 1.0f/s1, i2 = 1.0f/s2, i3 = 1.0f/s3;
    float* op = out + ((size_t)(r_s*Bn + b)*Kn)*HWn + p;
    #pragma unroll
    for (int k = 0; k < Kn; ++k) {
        float  ga = eGA_s[k*Hn + h];
        float4 gb = *(const float4*)(eGB_s + k*Wn + w);
        float4 ev = *(const float4*)(ea + (size_t)k*HWn);
        float4 v;
        v.x = ga * gb.x * ev.x * i0;
        v.y = ga * gb.y * ev.y * i1;
        v.z = ga * gb.z * ev.z * i2;
        v.w = ga * gb.w * ev.w * i3;
        *(float4*)(op + (size_t)k*HWn) = v;
    }
}

extern "C" void kernel_launch(void* const* d_in, const int* in_sizes, int n_in,
                              void* d_out, int out_size) {
    const float* x      = (const float*)d_in[0];
    const float* rois   = (const float*)d_in[1];
    const float* V_box  = (const float*)d_in[2];
    const float* W_box  = (const float*)d_in[3];
    const float* W_im   = (const float*)d_in[4];
    const float* conv_w = (const float*)d_in[5];
    const float* conv_b = (const float*)d_in[6];
    float* out = (float*)d_out;

    int smem_vapp = (56*256 + 64*64) * 4;    // 73.7 KB (app role is max)
    int smem_bvec = (32*128 + 64*130) * 4;   // 49.7 KB
    int smem_gab  = (2*32*GST) * 4;          // 66.6 KB
    cudaFuncSetAttribute(k_vapp, cudaFuncAttributeMaxDynamicSharedMemorySize, smem_vapp);
    cudaFuncSetAttribute(k_bvec, cudaFuncAttributeMaxDynamicSharedMemorySize, smem_bvec);
    cudaFuncSetAttribute(k_GAB,  cudaFuncAttributeMaxDynamicSharedMemorySize, smem_gab);

    k_pre  <<<Nn + Hn + Wn + 2 + 16, 256>>>(rois, W_im);
    k_vapp <<<256 + 192, 256, smem_vapp>>>(V_box, x, conv_w, conv_b);
    k_bvec <<<dim3(KOn/64, BSPLIT), 256, smem_bvec>>>(W_box);
    k_GAB  <<<dim3(Nn, 2, 4), 256, smem_gab>>>();
    k_final<<<dim3(HWn/1024, Nn*Bn), 256>>>(rois, out);
}

// round 14
// speedup vs baseline: 1.4526x; 1.0278x over previous
#include <cuda_runtime.h>
#include <math.h>

#define Dn   512
#define FDn  2048
#define On   256
#define Kn   49
#define Bn   4
#define Cn   256
#define Hn   64
#define Wn   48
#define HWn  3072
#define Nn   32
#define KOn  (Kn*On)     // 12544
#define KOP  16384       // padded 64*256
#define BSPLIT 4
#define GST  260         // k_GAB smem row stride

typedef unsigned long long u64;

__device__ float g_eps [Nn*FDn];
__device__ float g_v   [Nn*Dn];
__device__ float g_bvec[Nn*KOP];          // k padded to 64; slots >=49*256 stay 0
__device__ float g_A   [Hn*On];
__device__ float g_Bm  [Wn*On];
__device__ float g_eGA [Nn*Kn*Hn];
__device__ float g_eGB [Nn*Kn*Wn];
__device__ float g_eapp[Bn*Kn*HWn];

__device__ __forceinline__ void ffma2(u64 &acc, u64 a, u64 b) {
    asm volatile("fma.rn.f32x2 %0, %1, %2, %0;" : "+l"(acc) : "l"(a), "l"(b));
}
__device__ __forceinline__ float hsum2(u64 a) {
    float2 f = *reinterpret_cast<float2*>(&a);
    return f.x + f.y;
}

__device__ __forceinline__ float embed_val(float z, int dd) {
    float e = (dd < 256) ? (2.0f*dd + 1.0f)*(1.0f/512.0f) : (2.0f*(dd-256))*(1.0f/512.0f);
    float invden = exp2f(-e * 9.96578428466209f);   // 1000^-e
    double a = (double)z * (double)invden;
    double k = rint(a * 0.15915494309189535);
    float  r = (float)(a - k * 6.2831853071795864769);
    return (dd < 256) ? sinf(r) : cosf(r);
}

// ---------------- zero g_v (blocks 0,1) and g_bvec (blocks 2..17) ----------------
__global__ void k_zero() {
    int bid = blockIdx.x;
    if (bid < 2) {
        int base = bid * (Nn*Dn/2);
        for (int i = threadIdx.x; i < Nn*Dn/2; i += 256)
            g_v[base + i] = 0.0f;
    } else {
        int seg = bid - 2;     // 0..15
        int base = seg * (Nn*KOP/16);
        for (int i = threadIdx.x; i < Nn*KOP/16; i += 256)
            g_bvec[base + i] = 0.0f;
    }
}

// ---------------- fused: eps (0..31) | A/B (32..143) ----------------
__global__ void k_pre(const float* __restrict__ rois,
                      const float* __restrict__ W_im) {
    int bid = blockIdx.x;
    if (bid < Nn) {
        int n = bid;
        float c0 = rois[n*5+1], c1 = rois[n*5+2], c2 = rois[n*5+3], c3 = rois[n*5+4];
        for (int i = threadIdx.x; i < FDn; i += blockDim.x) {
            int c  = i >> 9;
            int dd = i & 511;
            float z = (c >= 2) ? ((c == 3) ? c3 : c2) : ((c == 1) ? c1 : c0);
            g_eps[n*FDn + i] = embed_val(z, dd);
        }
    } else {
        __shared__ __align__(16) float pe[Dn];
        int j = bid - Nn;
        bool isA = (j < Hn);
        float z = (float)(isA ? j : (j - Hn));
        for (int dd = threadIdx.x; dd < Dn; dd += blockDim.x)
            pe[dd] = embed_val(z, dd);
        __syncthreads();
        int o = threadIdx.x;
        const ulonglong2* w2 = (const ulonglong2*)(W_im + (size_t)o * (2*Dn) + (isA ? 0 : Dn));
        const ulonglong2* p2 = (const ulonglong2*)pe;
        u64 acc = 0;
        #pragma unroll 8
        for (int f = 0; f < Dn/4; ++f) {
            ulonglong2 wv = w2[f], pv = p2[f];
            ffma2(acc, wv.x, pv.x);
            ffma2(acc, wv.y, pv.y);
        }
        if (isA) g_A[j*On + o] = hsum2(acc);
        else     g_Bm[(j-Hn)*On + o] = hsum2(acc);
    }
}

// ================= fused v (blocks 0..255) + app (blocks 256..447) =============
__global__ void k_vapp(const float* __restrict__ V_box,
                       const float* __restrict__ x,
                       const float* __restrict__ conv_w,
                       const float* __restrict__ conv_b) {
    extern __shared__ __align__(16) float sm[];
    int bx = blockIdx.x;
    if (bx < 256) {
        // ---------------- v role ----------------
        float* eps_s = sm;             // [32 n][128 f]
        float* vt_s  = sm + 32*128;    // [32 d][130]
        int dp = bx >> 4, ks = bx & 15;
        int f0 = ks * 128;
        for (int i = threadIdx.x; i < 32*128; i += 256) {
            int n = i >> 7, f = i & 127;
            eps_s[i] = g_eps[n*FDn + f0 + f];
        }
        int srow = threadIdx.x >> 5, scol = threadIdx.x & 31;
        #pragma unroll
        for (int p = 0; p < 4; ++p) {
            int row = p*8 + srow;
            float4 vv = *(const float4*)(V_box + (size_t)(dp*32 + row)*FDn + f0 + scol*4);
            float* dst = vt_s + row*130 + scol*4;
            *(float2*)(dst)     = make_float2(vv.x, vv.y);
            *(float2*)(dst + 2) = make_float2(vv.z, vv.w);
        }
        __syncthreads();
        int dl = threadIdx.x & 31, ng = threadIdx.x >> 5;
        int d  = dp*32 + dl, n0 = ng*4;
        u64 acc[4] = {0,0,0,0};
        const float* vrow = vt_s + dl*130;
        #pragma unroll 8
        for (int fq = 0; fq < 32; ++fq) {
            u64 w0 = *(const u64*)(vrow + fq*4);
            u64 w1 = *(const u64*)(vrow + fq*4 + 2);
            #pragma unroll
            for (int j = 0; j < 4; ++j) {
                ulonglong2 ev = *(const ulonglong2*)(eps_s + (n0+j)*128 + fq*4);
                ffma2(acc[j], w0, ev.x);
                ffma2(acc[j], w1, ev.y);
            }
        }
        #pragma unroll
        for (int j = 0; j < 4; ++j)
            atomicAdd(&g_v[(size_t)(n0+j)*Dn + d], hsum2(acc[j]));
    } else {
        // ---------------- app role: smem weights, 2 px/thread, 7 k/group -------
        float* cw_s = sm;              // 56 x 256
        float* x_s  = sm + 56*256;     // 64 c x 64 p
        int r   = bx - 256;
        int b   = r / 48;
        int px0 = (r - b*48) * 64;
        for (int i = threadIdx.x; i < 56*256; i += 256) {
            int k = i >> 8, c = i & 255;
            cw_s[i] = (k < Kn) ? conv_w[k*Cn + c] : 0.0f;
        }
        int lane = threadIdx.x & 31;
        int kg   = threadIdx.x >> 5;
        int k0   = kg * 7;
        u64 acc[7];
        #pragma unroll
        for (int kk = 0; kk < 7; ++kk) acc[kk] = 0;

        for (int c0 = 0; c0 < Cn; c0 += 64) {
            __syncthreads();
            for (int i = threadIdx.x; i < 64*64; i += 256) {
                int c = i >> 6, p = i & 63;
                x_s[i] = x[((size_t)b*Cn + c0 + c)*HWn + px0 + p];
            }
            __syncthreads();
            #pragma unroll 4
            for (int c = 0; c < 64; ++c) {
                u64 xv = *(const u64*)(x_s + c*64 + lane*2);
                #pragma unroll
                for (int kk = 0; kk < 7; ++kk) {
                    float w = cw_s[(k0+kk)*256 + c0 + c];
                    u64 w2; asm("mov.b64 %0, {%1, %1};" : "=l"(w2) : "f"(w));
                    ffma2(acc[kk], w2, xv);
                }
            }
        }
        int p0 = px0 + lane*2;
        #pragma unroll
        for (int kk = 0; kk < 7; ++kk) {
            int k = k0 + kk;
            if (k < Kn) {
                float bias = conv_b[k];
                float2 a0 = *(float2*)&acc[kk];
                float2 v;
                v.x = expf(a0.x + bias);
                v.y = expf(a0.y + bias);
                *(float2*)(g_eapp + ((size_t)b*Kn + k)*HWn + p0) = v;
            }
        }
    }
}

// ---------------- bvec: grid (196 ko-tiles, 4 d-slices), atomic reduce ----------
__global__ void k_bvec(const float* __restrict__ W_box) {
    extern __shared__ __align__(16) float smb[];
    float* v_s  = smb;            // [32 n][128 f]
    float* wt_s = smb + 32*128;   // [64 ko][130]
    int ks = blockIdx.y;
    int f0 = ks * 128;
    int ko0 = blockIdx.x * 64;
    for (int i = threadIdx.x; i < 32*128; i += 256) {
        int n = i >> 7, fl = i & 127;
        v_s[i] = g_v[n*Dn + f0 + fl];
    }
    int srow = threadIdx.x >> 5, scol = threadIdx.x & 31;
    #pragma unroll
    for (int p = 0; p < 8; ++p) {
        int row = p*8 + srow;
        float4 wv = *(const float4*)(W_box + (size_t)(ko0 + row)*Dn + f0 + scol*4);
        float* dst = wt_s + row*130 + scol*4;
        *(float2*)(dst)     = make_float2(wv.x, wv.y);
        *(float2*)(dst + 2) = make_float2(wv.z, wv.w);
    }
    __syncthreads();
    int kol = threadIdx.x & 63;
    int ng  = threadIdx.x >> 6;
    int n0  = ng * 8;
    int ko  = ko0 + kol;
    int k   = ko >> 8, o = ko & 255;
    const float* wrow = wt_s + kol*130;
    u64 acc[8] = {0,0,0,0,0,0,0,0};
    #pragma unroll 4
    for (int fq = 0; fq < 32; ++fq) {
        u64 w0 = *(const u64*)(wrow + fq*4);
        u64 w1 = *(const u64*)(wrow + fq*4 + 2);
        #pragma unroll
        for (int j = 0; j < 8; ++j) {
            ulonglong2 vv = *(const ulonglong2*)(v_s + (n0+j)*128 + fq*4);
            ffma2(acc[j], w0, vv.x);
            ffma2(acc[j], w1, vv.y);
        }
    }
    #pragma unroll
    for (int j = 0; j < 8; ++j)
        atomicAdd(&g_bvec[(size_t)(n0+j)*KOP + k*256 + o], hsum2(acc[j]));
}

// -------- eGA/eGB: register-tiled GEMM, grid (n, side, lz*2+kz) ----------------
__global__ void k_GAB() {
    extern __shared__ __align__(16) float smg[];
    float* M_s  = smg;             // 32*GST
    float* bv_s = smg + 32*GST;    // 32*GST
    int n  = blockIdx.x;
    bool isA = (blockIdx.y == 0);
    int lz = blockIdx.z >> 1, kz = blockIdx.z & 1;
    int L    = isA ? Hn : Wn;
    int rows = isA ? 32 : 24;
    int loff = lz * rows;
    int k0   = kz * 32;
    const float* src = isA ? g_A : g_Bm;
    for (int i = threadIdx.x; i < rows*64; i += 256) {
        int r = i >> 6, o4 = i & 63;
        *(float4*)(M_s + r*GST + o4*4) =
            *(const float4*)(src + (size_t)(loff + r)*On + o4*4);
    }
    for (int i = threadIdx.x; i < 32*64; i += 256) {
        int r = i >> 6, o4 = i & 63;
        *(float4*)(bv_s + r*GST + o4*4) =
            *(const float4*)(g_bvec + (size_t)n*KOP + (size_t)(k0 + r)*On + o4*4);
    }
    __syncthreads();
    int lq = threadIdx.x & 15, kq = threadIdx.x >> 4;
    const float* m0 = M_s + lq*GST;
    const float* m1 = M_s + (lq + 16)*GST;
    const float* b0 = bv_s + (kq*2)*GST;
    const float* b1 = b0 + GST;
    float a00=0.f, a01=0.f, a10=0.f, a11=0.f;
    #pragma unroll 4
    for (int o4 = 0; o4 < 64; ++o4) {
        float4 ma = *(const float4*)(m0 + o4*4);
        float4 mb = *(const float4*)(m1 + o4*4);
        float4 ba = *(const float4*)(b0 + o4*4);
        float4 bb = *(const float4*)(b1 + o4*4);
        a00 += ma.x*ba.x + ma.y*ba.y + ma.z*ba.z + ma.w*ba.w;
        a01 += ma.x*bb.x + ma.y*bb.y + ma.z*bb.z + ma.w*bb.w;
        a10 += mb.x*ba.x + mb.y*ba.y + mb.z*ba.z + mb.w*ba.w;
        a11 += mb.x*bb.x + mb.y*bb.y + mb.z*bb.z + mb.w*bb.w;
    }
    int l0 = loff + lq;
    int l1 = loff + lq + 16;
    int k  = k0 + kq*2;
    bool l1ok = (lq + 16) < rows;
    float* dst = isA ? (g_eGA + (size_t)n*Kn*Hn) : (g_eGB + (size_t)n*Kn*Wn);
    if (k < Kn) {
        dst[k*L + l0] = expf(a00);
        if (l1ok) dst[k*L + l1] = expf(a10);
    }
    if (k + 1 < Kn) {
        dst[(k+1)*L + l0] = expf(a01);
        if (l1ok) dst[(k+1)*L + l1] = expf(a11);
    }
}

// ---------------- final: 4 px/thread, float4 I/O, softmax over k ----------------
__global__ void k_final(const float* __restrict__ rois, float* __restrict__ out) {
    __shared__ float eGA_s[Kn*Hn];
    __shared__ float eGB_s[Kn*Wn];
    __shared__ int r_s;
    int nb = blockIdx.y;
    int n = nb >> 2, b = nb & 3;
    if (threadIdx.x == 0) {
        int my = (int)rois[n*5];
        int r = 0;
        #pragma unroll
        for (int j = 0; j < Nn; ++j) {
            int o = (int)rois[j*5];
            r += (o < my) || (o == my && j < n);
        }
        r_s = r;
    }
    for (int i = threadIdx.x; i < Kn*Hn; i += 256) eGA_s[i] = g_eGA[n*Kn*Hn + i];
    for (int i = threadIdx.x; i < Kn*Wn; i += 256) eGB_s[i] = g_eGB[n*Kn*Wn + i];
    __syncthreads();
    int p = (blockIdx.x*256 + threadIdx.x) * 4;
    int h = p / 48;
    int w = p - h*48;
    const float* ea = g_eapp + (size_t)b*Kn*HWn + p;
    float s0 = 0.f, s1 = 0.f, s2 = 0.f, s3 = 0.f;
    #pragma unroll
    for (int k = 0; k < Kn; ++k) {
        float  ga = eGA_s[k*Hn + h];
        float4 gb = *(const float4*)(eGB_s + k*Wn + w);
        float4 ev = *(const float4*)(ea + (size_t)k*HWn);
        s0 += ga * gb.x * ev.x;
        s1 += ga * gb.y * ev.y;
        s2 += ga * gb.z * ev.z;
        s3 += ga * gb.w * ev.w;
    }
    float i0 = 1.0f/s0, i1 = 1.0f/s1, i2 = 1.0f/s2, i3 = 1.0f/s3;
    float* op = out + ((size_t)(r_s*Bn + b)*Kn)*HWn + p;
    #pragma unroll
    for (int k = 0; k < Kn; ++k) {
        float  ga = eGA_s[k*Hn + h];
        float4 gb = *(const float4*)(eGB_s + k*Wn + w);
        float4 ev = *(const float4*)(ea + (size_t)k*HWn);
        float4 v;
        v.x = ga * gb.x * ev.x * i0;
        v.y = ga * gb.y * ev.y * i1;
        v.z = ga * gb.z * ev.z * i2;
        v.w = ga * gb.w * ev.w * i3;
        *(float4*)(op + (size_t)k*HWn) = v;
    }
}

extern "C" void kernel_launch(void* const* d_in, const int* in_sizes, int n_in,
                              void* d_out, int out_size) {
    const float* x      = (const float*)d_in[0];
    const float* rois   = (const float*)d_in[1];
    const float* V_box  = (const float*)d_in[2];
    const float* W_box  = (const float*)d_in[3];
    const float* W_im   = (const float*)d_in[4];
    const float* conv_w = (const float*)d_in[5];
    const float* conv_b = (const float*)d_in[6];
    float* out = (float*)d_out;

    int smem_vapp = (56*256 + 64*64) * 4;    // 73.7 KB (app role is max)
    int smem_bvec = (32*128 + 64*130) * 4;   // 49.7 KB
    int smem_gab  = (2*32*GST) * 4;          // 66.6 KB
    cudaFuncSetAttribute(k_vapp, cudaFuncAttributeMaxDynamicSharedMemorySize, smem_vapp);
    cudaFuncSetAttribute(k_bvec, cudaFuncAttributeMaxDynamicSharedMemorySize, smem_bvec);
    cudaFuncSetAttribute(k_GAB,  cudaFuncAttributeMaxDynamicSharedMemorySize, smem_gab);

    k_zero <<<18, 256>>>();
    k_pre  <<<Nn + Hn + Wn, 256>>>(rois, W_im);
    k_vapp <<<256 + 192, 256, smem_vapp>>>(V_box, x, conv_w, conv_b);
    k_bvec <<<dim3(KOn/64, BSPLIT), 256, smem_bvec>>>(W_box);
    k_GAB  <<<dim3(Nn, 2, 4), 256, smem_gab>>>();
    k_final<<<dim3(HWn/1024, Nn*Bn), 256>>>(rois, out);
}

// round 15
// speedup vs baseline: 1.5215x; 1.0474x over previous
#include <cuda_runtime.h>
#include <math.h>

#define Dn   512
#define FDn  2048
#define On   256
#define Kn   49
#define Bn   4
#define Cn   256
#define Hn   64
#define Wn   48
#define HWn  3072
#define Nn   32
#define KOn  (Kn*On)     // 12544
#define KOP  16384       // padded 64*256
#define BSPLIT 8
#define GST  260         // k_GAB smem row stride
#define BST  68          // k_bvec wt smem row stride (64 + 4 pad, 16B aligned)

typedef unsigned long long u64;

__device__ float g_eps [Nn*FDn];
__device__ float g_v   [Nn*Dn];
__device__ float g_bvec[Nn*KOP];          // k padded to 64; slots >=49*256 stay 0
__device__ float g_A   [Hn*On];
__device__ float g_Bm  [Wn*On];
__device__ float g_eGA [Nn*Kn*Hn];
__device__ float g_eGB [Nn*Kn*Wn];
__device__ float g_eapp[Bn*Kn*HWn];

__device__ __forceinline__ void ffma2(u64 &acc, u64 a, u64 b) {
    asm volatile("fma.rn.f32x2 %0, %1, %2, %0;" : "+l"(acc) : "l"(a), "l"(b));
}
__device__ __forceinline__ float hsum2(u64 a) {
    float2 f = *reinterpret_cast<float2*>(&a);
    return f.x + f.y;
}

__device__ __forceinline__ float embed_val(float z, int dd) {
    float e = (dd < 256) ? (2.0f*dd + 1.0f)*(1.0f/512.0f) : (2.0f*(dd-256))*(1.0f/512.0f);
    float invden = exp2f(-e * 9.96578428466209f);   // 1000^-e
    double a = (double)z * (double)invden;
    double k = rint(a * 0.15915494309189535);
    float  r = (float)(a - k * 6.2831853071795864769);
    return (dd < 256) ? sinf(r) : cosf(r);
}

// ---------------- zero g_v (blocks 0,1) and g_bvec (blocks 2..17) ----------------
__global__ void k_zero() {
    int bid = blockIdx.x;
    if (bid < 2) {
        int base = bid * (Nn*Dn/2);
        for (int i = threadIdx.x; i < Nn*Dn/2; i += 256)
            g_v[base + i] = 0.0f;
    } else {
        int seg = bid - 2;     // 0..15
        int base = seg * (Nn*KOP/16);
        for (int i = threadIdx.x; i < Nn*KOP/16; i += 256)
            g_bvec[base + i] = 0.0f;
    }
}

// ---------------- fused: eps (0..31) | A/B (32..143) ----------------
__global__ void k_pre(const float* __restrict__ rois,
                      const float* __restrict__ W_im) {
    int bid = blockIdx.x;
    if (bid < Nn) {
        int n = bid;
        float c0 = rois[n*5+1], c1 = rois[n*5+2], c2 = rois[n*5+3], c3 = rois[n*5+4];
        for (int i = threadIdx.x; i < FDn; i += blockDim.x) {
            int c  = i >> 9;
            int dd = i & 511;
            float z = (c >= 2) ? ((c == 3) ? c3 : c2) : ((c == 1) ? c1 : c0);
            g_eps[n*FDn + i] = embed_val(z, dd);
        }
    } else {
        __shared__ __align__(16) float pe[Dn];
        int j = bid - Nn;
        bool isA = (j < Hn);
        float z = (float)(isA ? j : (j - Hn));
        for (int dd = threadIdx.x; dd < Dn; dd += blockDim.x)
            pe[dd] = embed_val(z, dd);
        __syncthreads();
        int o = threadIdx.x;
        const ulonglong2* w2 = (const ulonglong2*)(W_im + (size_t)o * (2*Dn) + (isA ? 0 : Dn));
        const ulonglong2* p2 = (const ulonglong2*)pe;
        u64 acc = 0;
        #pragma unroll 8
        for (int f = 0; f < Dn/4; ++f) {
            ulonglong2 wv = w2[f], pv = p2[f];
            ffma2(acc, wv.x, pv.x);
            ffma2(acc, wv.y, pv.y);
        }
        if (isA) g_A[j*On + o] = hsum2(acc);
        else     g_Bm[(j-Hn)*On + o] = hsum2(acc);
    }
}

// ================= fused v (blocks 0..255) + app (blocks 256..447) =============
__global__ void k_vapp(const float* __restrict__ V_box,
                       const float* __restrict__ x,
                       const float* __restrict__ conv_w,
                       const float* __restrict__ conv_b) {
    extern __shared__ __align__(16) float sm[];
    int bx = blockIdx.x;
    if (bx < 256) {
        // ---------------- v role ----------------
        float* eps_s = sm;             // [32 n][128 f]
        float* vt_s  = sm + 32*128;    // [32 d][130]
        int dp = bx >> 4, ks = bx & 15;
        int f0 = ks * 128;
        for (int i = threadIdx.x; i < 32*128; i += 256) {
            int n = i >> 7, f = i & 127;
            eps_s[i] = g_eps[n*FDn + f0 + f];
        }
        int srow = threadIdx.x >> 5, scol = threadIdx.x & 31;
        #pragma unroll
        for (int p = 0; p < 4; ++p) {
            int row = p*8 + srow;
            float4 vv = *(const float4*)(V_box + (size_t)(dp*32 + row)*FDn + f0 + scol*4);
            float* dst = vt_s + row*130 + scol*4;
            *(float2*)(dst)     = make_float2(vv.x, vv.y);
            *(float2*)(dst + 2) = make_float2(vv.z, vv.w);
        }
        __syncthreads();
        int dl = threadIdx.x & 31, ng = threadIdx.x >> 5;
        int d  = dp*32 + dl, n0 = ng*4;
        u64 acc[4] = {0,0,0,0};
        const float* vrow = vt_s + dl*130;
        #pragma unroll 8
        for (int fq = 0; fq < 32; ++fq) {
            u64 w0 = *(const u64*)(vrow + fq*4);
            u64 w1 = *(const u64*)(vrow + fq*4 + 2);
            #pragma unroll
            for (int j = 0; j < 4; ++j) {
                ulonglong2 ev = *(const ulonglong2*)(eps_s + (n0+j)*128 + fq*4);
                ffma2(acc[j], w0, ev.x);
                ffma2(acc[j], w1, ev.y);
            }
        }
        #pragma unroll
        for (int j = 0; j < 4; ++j)
            atomicAdd(&g_v[(size_t)(n0+j)*Dn + d], hsum2(acc[j]));
    } else {
        // ---------------- app role: smem weights, 2 px/thread, 7 k/group -------
        float* cw_s = sm;              // 56 x 256
        float* x_s  = sm + 56*256;     // 64 c x 64 p
        int r   = bx - 256;
        int b   = r / 48;
        int px0 = (r - b*48) * 64;
        for (int i = threadIdx.x; i < 56*256; i += 256) {
            int k = i >> 8, c = i & 255;
            cw_s[i] = (k < Kn) ? conv_w[k*Cn + c] : 0.0f;
        }
        int lane = threadIdx.x & 31;
        int kg   = threadIdx.x >> 5;
        int k0   = kg * 7;
        u64 acc[7];
        #pragma unroll
        for (int kk = 0; kk < 7; ++kk) acc[kk] = 0;

        for (int c0 = 0; c0 < Cn; c0 += 64) {
            __syncthreads();
            for (int i = threadIdx.x; i < 64*64; i += 256) {
                int c = i >> 6, p = i & 63;
                x_s[i] = x[((size_t)b*Cn + c0 + c)*HWn + px0 + p];
            }
            __syncthreads();
            #pragma unroll 4
            for (int c = 0; c < 64; ++c) {
                u64 xv = *(const u64*)(x_s + c*64 + lane*2);
                #pragma unroll
                for (int kk = 0; kk < 7; ++kk) {
                    float w = cw_s[(k0+kk)*256 + c0 + c];
                    u64 w2; asm("mov.b64 %0, {%1, %1};" : "=l"(w2) : "f"(w));
                    ffma2(acc[kk], w2, xv);
                }
            }
        }
        int p0 = px0 + lane*2;
        #pragma unroll
        for (int kk = 0; kk < 7; ++kk) {
            int k = k0 + kk;
            if (k < Kn) {
                float bias = conv_b[k];
                float2 a0 = *(float2*)&acc[kk];
                float2 v;
                v.x = expf(a0.x + bias);
                v.y = expf(a0.y + bias);
                *(float2*)(g_eapp + ((size_t)b*Kn + k)*HWn + p0) = v;
            }
        }
    }
}

// ------- bvec: grid (196 ko-tiles, 8 f-slices of 64), high-occupancy ----------
__global__ void __launch_bounds__(256, 6) k_bvec(const float* __restrict__ W_box) {
    __shared__ __align__(16) float v_s [Nn*64];     // 8 KB
    __shared__ __align__(16) float wt_s[64*BST];    // 17.4 KB
    int ks = blockIdx.y;
    int f0 = ks * 64;
    int ko0 = blockIdx.x * 64;
    for (int i = threadIdx.x; i < Nn*64; i += 256)
        v_s[i] = g_v[(i >> 6)*Dn + f0 + (i & 63)];
    #pragma unroll
    for (int q = 0; q < 4; ++q) {
        int idx = q*256 + threadIdx.x;          // float4 units, 0..1023
        int row = idx >> 4, f4 = idx & 15;
        float4 wv = *(const float4*)(W_box + (size_t)(ko0 + row)*Dn + f0 + f4*4);
        *(float4*)(wt_s + row*BST + f4*4) = wv;
    }
    __syncthreads();
    int kol = threadIdx.x & 63;
    int ng  = threadIdx.x >> 6;
    int n0  = ng * 8;
    int ko  = ko0 + kol;
    int k   = ko >> 8, o = ko & 255;
    const float* wrow = wt_s + kol*BST;
    u64 acc[8] = {0,0,0,0,0,0,0,0};
    #pragma unroll 4
    for (int fq = 0; fq < 16; ++fq) {
        float4 w4 = *(const float4*)(wrow + fq*4);
        u64 w0 = ((const u64*)&w4)[0];
        u64 w1 = ((const u64*)&w4)[1];
        #pragma unroll
        for (int j = 0; j < 8; ++j) {
            ulonglong2 vv = *(const ulonglong2*)(v_s + (n0+j)*64 + fq*4);
            ffma2(acc[j], w0, vv.x);
            ffma2(acc[j], w1, vv.y);
        }
    }
    #pragma unroll
    for (int j = 0; j < 8; ++j)
        atomicAdd(&g_bvec[(size_t)(n0+j)*KOP + k*256 + o], hsum2(acc[j]));
}

// -------- eGA/eGB: register-tiled GEMM, grid (n, side, lz*2+kz) ----------------
__global__ void k_GAB() {
    extern __shared__ __align__(16) float smg[];
    float* M_s  = smg;             // 32*GST
    float* bv_s = smg + 32*GST;    // 32*GST
    int n  = blockIdx.x;
    bool isA = (blockIdx.y == 0);
    int lz = blockIdx.z >> 1, kz = blockIdx.z & 1;
    int L    = isA ? Hn : Wn;
    int rows = isA ? 32 : 24;
    int loff = lz * rows;
    int k0   = kz * 32;
    const float* src = isA ? g_A : g_Bm;
    for (int i = threadIdx.x; i < rows*64; i += 256) {
        int r = i >> 6, o4 = i & 63;
        *(float4*)(M_s + r*GST + o4*4) =
            *(const float4*)(src + (size_t)(loff + r)*On + o4*4);
    }
    for (int i = threadIdx.x; i < 32*64; i += 256) {
        int r = i >> 6, o4 = i & 63;
        *(float4*)(bv_s + r*GST + o4*4) =
            *(const float4*)(g_bvec + (size_t)n*KOP + (size_t)(k0 + r)*On + o4*4);
    }
    __syncthreads();
    int lq = threadIdx.x & 15, kq = threadIdx.x >> 4;
    const float* m0 = M_s + lq*GST;
    const float* m1 = M_s + (lq + 16)*GST;
    const float* b0 = bv_s + (kq*2)*GST;
    const float* b1 = b0 + GST;
    float a00=0.f, a01=0.f, a10=0.f, a11=0.f;
    #pragma unroll 4
    for (int o4 = 0; o4 < 64; ++o4) {
        float4 ma = *(const float4*)(m0 + o4*4);
        float4 mb = *(const float4*)(m1 + o4*4);
        float4 ba = *(const float4*)(b0 + o4*4);
        float4 bb = *(const float4*)(b1 + o4*4);
        a00 += ma.x*ba.x + ma.y*ba.y + ma.z*ba.z + ma.w*ba.w;
        a01 += ma.x*bb.x + ma.y*bb.y + ma.z*bb.z + ma.w*bb.w;
        a10 += mb.x*ba.x + mb.y*ba.y + mb.z*ba.z + mb.w*ba.w;
        a11 += mb.x*bb.x + mb.y*bb.y + mb.z*bb.z + mb.w*bb.w;
    }
    int l0 = loff + lq;
    int l1 = loff + lq + 16;
    int k  = k0 + kq*2;
    bool l1ok = (lq + 16) < rows;
    float* dst = isA ? (g_eGA + (size_t)n*Kn*Hn) : (g_eGB + (size_t)n*Kn*Wn);
    if (k < Kn) {
        dst[k*L + l0] = expf(a00);
        if (l1ok) dst[k*L + l1] = expf(a10);
    }
    if (k + 1 < Kn) {
        dst[(k+1)*L + l0] = expf(a01);
        if (l1ok) dst[(k+1)*L + l1] = expf(a11);
    }
}

// ---------------- final: 4 px/thread, float4 I/O, softmax over k ----------------
__global__ void k_final(const float* __restrict__ rois, float* __restrict__ out) {
    __shared__ float eGA_s[Kn*Hn];
    __shared__ float eGB_s[Kn*Wn];
    __shared__ int r_s;
    int nb = blockIdx.y;
    int n = nb >> 2, b = nb & 3;
    if (threadIdx.x == 0) {
        int my = (int)rois[n*5];
        int r = 0;
        #pragma unroll
        for (int j = 0; j < Nn; ++j) {
            int o = (int)rois[j*5];
            r += (o < my) || (o == my && j < n);
        }
        r_s = r;
    }
    for (int i = threadIdx.x; i < Kn*Hn; i += 256) eGA_s[i] = g_eGA[n*Kn*Hn + i];
    for (int i = threadIdx.x; i < Kn*Wn; i += 256) eGB_s[i] = g_eGB[n*Kn*Wn + i];
    __syncthreads();
    int p = (blockIdx.x*256 + threadIdx.x) * 4;
    int h = p / 48;
    int w = p - h*48;
    const float* ea = g_eapp + (size_t)b*Kn*HWn + p;
    float s0 = 0.f, s1 = 0.f, s2 = 0.f, s3 = 0.f;
    #pragma unroll
    for (int k = 0; k < Kn; ++k) {
        float  ga = eGA_s[k*Hn + h];
        float4 gb = *(const float4*)(eGB_s + k*Wn + w);
        float4 ev = *(const float4*)(ea + (size_t)k*HWn);
        s0 += ga * gb.x * ev.x;
        s1 += ga * gb.y * ev.y;
        s2 += ga * gb.z * ev.z;
        s3 += ga * gb.w * ev.w;
    }
    float i0 = 1.0f/s0, i1 = 1.0f/s1, i2 = 1.0f/s2, i3 = 1.0f/s3;
    float* op = out + ((size_t)(r_s*Bn + b)*Kn)*HWn + p;
    #pragma unroll
    for (int k = 0; k < Kn; ++k) {
        float  ga = eGA_s[k*Hn + h];
        float4 gb = *(const float4*)(eGB_s + k*Wn + w);
        float4 ev = *(const float4*)(ea + (size_t)k*HWn);
        float4 v;
        v.x = ga * gb.x * ev.x * i0;
        v.y = ga * gb.y * ev.y * i1;
        v.z = ga * gb.z * ev.z * i2;
        v.w = ga * gb.w * ev.w * i3;
        *(float4*)(op + (size_t)k*HWn) = v;
    }
}

extern "C" void kernel_launch(void* const* d_in, const int* in_sizes, int n_in,
                              void* d_out, int out_size) {
    const float* x      = (const float*)d_in[0];
    const float* rois   = (const float*)d_in[1];
    const float* V_box  = (const float*)d_in[2];
    const float* W_box  = (const float*)d_in[3];
    const float* W_im   = (const float*)d_in[4];
    const float* conv_w = (const float*)d_in[5];
    const float* conv_b = (const float*)d_in[6];
    float* out = (float*)d_out;

    int smem_vapp = (56*256 + 64*64) * 4;    // 73.7 KB (app role is max)
    int smem_gab  = (2*32*GST) * 4;          // 66.6 KB
    cudaFuncSetAttribute(k_vapp, cudaFuncAttributeMaxDynamicSharedMemorySize, smem_vapp);
    cudaFuncSetAttribute(k_GAB,  cudaFuncAttributeMaxDynamicSharedMemorySize, smem_gab);

    k_zero <<<18, 256>>>();
    k_pre  <<<Nn + Hn + Wn, 256>>>(rois, W_im);
    k_vapp <<<256 + 192, 256, smem_vapp>>>(V_box, x, conv_w, conv_b);
    k_bvec <<<dim3(KOn/64, BSPLIT), 256>>>(W_box);
    k_GAB  <<<dim3(Nn, 2, 4), 256, smem_gab>>>();
    k_final<<<dim3(HWn/1024, Nn*Bn), 256>>>(rois, out);
}